// round 1
// baseline (speedup 1.0000x reference)
#include <cuda_runtime.h>
#include <cuda_bf16.h>
#include <cstdint>

// Problem shape (BGEM3 sparse-embedding head)
#define BB 32
#define SS 1024
#define HH 1024
#define VV 250002

// One warp per (b,s) row. 8 warps (256 threads) per block.
// hidden row = 1024 floats = 256 float4, contiguous -> coalesced.
__global__ __launch_bounds__(256) void bgem3_dot_scatter(
    const float4* __restrict__ hidden,   // [B*S, H/4] as float4
    const int*    __restrict__ ids,      // [B*S]
    const float4* __restrict__ W4,       // [H/4]
    const float*  __restrict__ bias,     // [1]
    float*        __restrict__ out)      // [B, V], pre-zeroed
{
    __shared__ float4 w[HH / 4];  // 4 KB

    const int tid  = threadIdx.x;
    // Stage W into shared memory once per block (256 float4 = 256 threads)
    w[tid] = W4[tid];
    __syncthreads();

    const int warp = tid >> 5;
    const int lane = tid & 31;
    const int row  = blockIdx.x * 8 + warp;      // [0, B*S)

    const float4* h = hidden + (size_t)row * (HH / 4);

    float sum = 0.0f;
#pragma unroll
    for (int i = 0; i < 8; i++) {
        const int idx = lane + i * 32;
        const float4 hv = h[idx];
        const float4 wv = w[idx];
        sum += hv.x * wv.x + hv.y * wv.y + hv.z * wv.z + hv.w * wv.w;
    }

    // warp-level tree reduction
#pragma unroll
    for (int off = 16; off > 0; off >>= 1)
        sum += __shfl_xor_sync(0xFFFFFFFFu, sum, off);

    if (lane == 0) {
        const float tw = sum + bias[0];
        if (tw > 0.0f) {
            const int token = ids[row];
            // tokens 0..3 are masked to zero in the reference; since the
            // table is zero-initialized, skipping them is equivalent.
            if (token >= 4) {
                const int b = row / SS;
                // post-ReLU weights are >= 0 and table init is 0, so the
                // IEEE-754 bit pattern is monotone as a signed int:
                // integer atomicMax == float max, exactly.
                atomicMax(reinterpret_cast<int*>(out + (size_t)b * VV + token),
                          __float_as_int(tw));
            }
        }
    }
}

extern "C" void kernel_launch(void* const* d_in, const int* in_sizes, int n_in,
                              void* d_out, int out_size)
{
    const float4* hidden = (const float4*)d_in[0];  // [B,S,H] f32
    const int*    ids    = (const int*)d_in[1];     // [B,S] i32
    const float4* W4     = (const float4*)d_in[2];  // [1,H] f32
    const float*  bias   = (const float*)d_in[3];   // [1] f32
    float*        out    = (float*)d_out;           // [B,V] f32

    // Zero the output table (graph-capturable memset node).
    cudaMemsetAsync(d_out, 0, (size_t)out_size * sizeof(float));

    const int rows = BB * SS;            // 32768
    const int blocks = rows / 8;         // 4096 blocks x 256 threads
    bgem3_dot_scatter<<<blocks, 256>>>(hidden, ids, W4, bias, out);
}

// round 2
// speedup vs baseline: 1.0642x; 1.0642x over previous
#include <cuda_runtime.h>
#include <cuda_bf16.h>
#include <cstdint>

// Problem shape (BGEM3 sparse-embedding head)
#define BB 32
#define SS 1024
#define HH 1024
#define VV 250002

#define ROWS      (BB * SS)          // 32768
#define OUT_F4    ((BB * VV) / 4)    // 2000016 float4 (B*V divisible by 4)

#define CBLOCKS   4096               // compute blocks: 8 warps * 1 row/warp
#define ZBLOCKS   1024               // zero blocks
#define NBLOCKS   (CBLOCKS + ZBLOCKS)
#define ZTHREADS  (ZBLOCKS * 256)    // 262144
#define ZITERS    8                  // ceil(OUT_F4 / ZTHREADS) = 7.63 -> 8

// Scratch for per-row token weights (written fully every call; deterministic).
__device__ float g_tw[ROWS];

// Fused kernel: 4 of every 5 blocks compute dot products -> g_tw,
// 1 of every 5 blocks zeros the output table. Independent tasks, one wave,
// read (128MB) + write (32MB) streams mix on HBM.
__global__ __launch_bounds__(256) void bgem3_fused(
    const float4* __restrict__ hidden,   // [B*S, H/4]
    const float4* __restrict__ W4,       // [H/4]
    const float*  __restrict__ bias,     // [1]
    float4*       __restrict__ out4)     // [B*V/4], to be zeroed
{
    const int bid = blockIdx.x;
    const int tid = threadIdx.x;

    if ((bid % 5) == 4) {
        // ---- zero role ----
        const int zb = bid / 5;                 // 0..ZBLOCKS-1
        const float4 z = make_float4(0.f, 0.f, 0.f, 0.f);
        int idx = zb * 256 + tid;
#pragma unroll
        for (int i = 0; i < ZITERS; i++) {
            if (idx < OUT_F4) out4[idx] = z;
            idx += ZTHREADS;
        }
        return;
    }

    // ---- compute role ----
    const int cid = (bid / 5) * 4 + (bid % 5);  // 0..CBLOCKS-1

    __shared__ float4 w[HH / 4];                // 4 KB
    w[tid] = W4[tid];
    __syncthreads();

    const int warp = tid >> 5;
    const int lane = tid & 31;
    const int row  = cid * 8 + warp;            // [0, ROWS)

    const float4* h = hidden + (size_t)row * (HH / 4);

    float sum = 0.0f;
#pragma unroll
    for (int i = 0; i < 8; i++) {
        const int idx = lane + i * 32;
        const float4 hv = h[idx];
        const float4 wv = w[idx];
        sum += hv.x * wv.x + hv.y * wv.y + hv.z * wv.z + hv.w * wv.w;
    }

#pragma unroll
    for (int off = 16; off > 0; off >>= 1)
        sum += __shfl_xor_sync(0xFFFFFFFFu, sum, off);

    if (lane == 0) {
        const float tw = fmaxf(sum + bias[0], 0.0f);   // ReLU
        g_tw[row] = tw;
    }
}

// Tiny scatter kernel: runs after zeroing + tw are both done.
__global__ __launch_bounds__(256) void bgem3_scatter(
    const int* __restrict__ ids,   // [B*S]
    float*     __restrict__ out)   // [B, V], zeroed by bgem3_fused
{
    const int row = blockIdx.x * 256 + threadIdx.x;   // [0, ROWS)
    const float tw = g_tw[row];
    if (tw > 0.0f) {
        const int token = ids[row];
        // tokens 0..3 are masked to zero in the reference; table is zeroed,
        // so skipping them is equivalent.
        if (token >= 4) {
            const int b = row >> 10;                  // row / SS
            // Post-ReLU weights >= 0 and table init is 0 -> IEEE-754 bits are
            // monotone as signed int: integer atomicMax == exact float max.
            atomicMax(reinterpret_cast<int*>(out + (size_t)b * VV + token),
                      __float_as_int(tw));
        }
    }
}

extern "C" void kernel_launch(void* const* d_in, const int* in_sizes, int n_in,
                              void* d_out, int out_size)
{
    const float4* hidden = (const float4*)d_in[0];  // [B,S,H] f32
    const int*    ids    = (const int*)d_in[1];     // [B,S] i32
    const float4* W4     = (const float4*)d_in[2];  // [1,H] f32
    const float*  bias   = (const float*)d_in[3];   // [1] f32
    float*        out    = (float*)d_out;           // [B,V] f32

    bgem3_fused<<<NBLOCKS, 256>>>(hidden, W4, bias, (float4*)d_out);
    bgem3_scatter<<<ROWS / 256, 256>>>(ids, out);
}